// round 14
// baseline (speedup 1.0000x reference)
#include <cuda_runtime.h>
#include <cuda_fp16.h>
#include <cstdint>
#include <cstddef>

#define B_   16
#define N_   4096
#define M_   1024
#define C1_  256
#define C2_  256
#define CO_  256

// GEMM tile geometry: 128co x 128n per block, 2 CTAs/SM, single-pass fp16
#define TM 128
#define TN 128
#define KC 32
#define ROWE 40               // fp16 elems per smem row (32 data + 8 pad) = 80B
#define ROWB 80
#define A_STAGE 10240         // 128 rows * 80B
#define B_BASE_ 20480
#define B_STAGE 10240
#define SMEM_TOTAL 40960

// ---------------- scratch (device globals) ------------------------------------
__device__ float g_interp[(size_t)B_ * C2_ * N_];
__device__ float g_h1[(size_t)B_ * CO_ * N_];
__device__ float g_h2[(size_t)B_ * CO_ * N_];
__device__ int   g_idx[(size_t)B_ * 3 * N_];
__device__ float g_w[(size_t)B_ * 3 * N_];
__device__ float g_pd[(size_t)B_ * 4 * 3 * N_];
__device__ int   g_pi[(size_t)B_ * 4 * 3 * N_];
__device__ float g_sum1[CO_], g_sq1[CO_], g_scale1[CO_], g_shift1[CO_];
__device__ float g_sum2[CO_], g_sq2[CO_], g_scale2[CO_], g_shift2[CO_];
// fp16 weight smem-images: [chunk][256 co][ROWE]
__device__ __half g_w1img[16 * 256 * ROWE];
__device__ __half g_w2img[8 * 256 * ROWE];

// ---------------- helpers ------------------------------------------------------
__device__ __forceinline__ uint32_t smem_u32(const void* p) {
    uint32_t a;
    asm("{ .reg .u64 t; cvta.to.shared.u64 t, %1; cvt.u32.u64 %0, t; }" : "=r"(a) : "l"(p));
    return a;
}
#define CP_ASYNC16(dst, src) \
    asm volatile("cp.async.cg.shared.global [%0], [%1], 16;" :: "r"(dst), "l"(src))
#define CP_COMMIT() asm volatile("cp.async.commit_group;")
#define CP_WAIT0()  asm volatile("cp.async.wait_group 0;")

__device__ __forceinline__ void mma16816(float c[4], const uint32_t a[4], const uint32_t b[2]) {
    asm volatile(
        "mma.sync.aligned.m16n8k16.row.col.f32.f16.f16.f32 "
        "{%0,%1,%2,%3}, {%4,%5,%6,%7}, {%8,%9}, {%0,%1,%2,%3};"
        : "+f"(c[0]), "+f"(c[1]), "+f"(c[2]), "+f"(c[3])
        : "r"(a[0]), "r"(a[1]), "r"(a[2]), "r"(a[3]), "r"(b[0]), "r"(b[1]));
}
__device__ __forceinline__ void ldmx4(uint32_t r[4], uint32_t addr) {
    asm volatile("ldmatrix.sync.aligned.m8n8.x4.shared.b16 {%0,%1,%2,%3}, [%4];"
                 : "=r"(r[0]), "=r"(r[1]), "=r"(r[2]), "=r"(r[3]) : "r"(addr));
}

// ---------------- weight fp16 image (+stats zero folded in) ---------------------
__global__ void wsplit_img_kernel(const float* __restrict__ W, int Kdim, int total,
                                  __half* __restrict__ out, int do_zero) {
    int idx = blockIdx.x * 256 + threadIdx.x;
    if (do_zero && blockIdx.x == 0) {
        int t = threadIdx.x;
        g_sum1[t] = 0.f; g_sq1[t] = 0.f;
        g_sum2[t] = 0.f; g_sq2[t] = 0.f;
    }
    if (idx >= total) return;
    int kk = idx % ROWE;
    int co = (idx / ROWE) & 255;
    int chunk = idx / (ROWE * 256);
    float v = (kk < KC) ? W[(size_t)co * Kdim + chunk * KC + kk] : 0.f;
    out[idx] = __float2half_rn(v);
}

// ---------------- chunked three_nn: 4 queries per thread --------------------------
__global__ void __launch_bounds__(128) knn_part_kernel(
    const float* __restrict__ unknown, const float* __restrict__ known) {
    __shared__ float4 sk[256];
    int b = blockIdx.z, ch = blockIdx.y;
    const float* kb = known + ((size_t)b * M_ + ch * 256) * 3;
    for (int j = threadIdx.x; j < 256; j += 128)
        sk[j] = make_float4(kb[j * 3 + 0], kb[j * 3 + 1], kb[j * 3 + 2], 0.f);
    __syncthreads();

    int qbase = blockIdx.x * 512 + threadIdx.x;   // queries qbase + q*128
    float px[4], py[4], pz[4];
    float bd0[4], bd1[4], bd2[4];
    int   bi0[4], bi1[4], bi2[4];
    #pragma unroll
    for (int q = 0; q < 4; ++q) {
        const float* up = unknown + ((size_t)b * N_ + qbase + q * 128) * 3;
        px[q] = up[0]; py[q] = up[1]; pz[q] = up[2];
        bd0[q] = 1e30f; bd1[q] = 1e30f; bd2[q] = 1e30f;
        bi0[q] = 0; bi1[q] = 0; bi2[q] = 0;
    }

    #pragma unroll 2
    for (int j = 0; j < 256; ++j) {
        float4 k4 = sk[j];
        #pragma unroll
        for (int q = 0; q < 4; ++q) {
            float dx = px[q] - k4.x, dy = py[q] - k4.y, dz = pz[q] - k4.z;
            float d = dx * dx + dy * dy + dz * dz;
            if (d < bd2[q]) {
                if (d < bd1[q]) {
                    bd2[q] = bd1[q]; bi2[q] = bi1[q];
                    if (d < bd0[q]) { bd1[q] = bd0[q]; bi1[q] = bi0[q]; bd0[q] = d; bi0[q] = j; }
                    else            { bd1[q] = d;      bi1[q] = j; }
                } else { bd2[q] = d; bi2[q] = j; }
            }
        }
    }

    int gofs = ch * 256;
    #pragma unroll
    for (int q = 0; q < 4; ++q) {
        size_t base = (((size_t)b * 4 + ch) * 3) * N_ + qbase + q * 128;
        g_pd[base + 0 * N_] = bd0[q]; g_pi[base + 0 * N_] = bi0[q] + gofs;
        g_pd[base + 1 * N_] = bd1[q]; g_pi[base + 1 * N_] = bi1[q] + gofs;
        g_pd[base + 2 * N_] = bd2[q]; g_pi[base + 2 * N_] = bi2[q] + gofs;
    }
}

__global__ void __launch_bounds__(128) knn_merge_kernel() {
    int b = blockIdx.y;
    int i = blockIdx.x * 128 + threadIdx.x;
    float bd0 = 1e30f, bd1 = 1e30f, bd2 = 1e30f;
    int   bi0 = 0, bi1 = 0, bi2 = 0;
    #pragma unroll
    for (int ch = 0; ch < 4; ++ch) {
        #pragma unroll
        for (int t = 0; t < 3; ++t) {
            size_t base = (((size_t)b * 4 + ch) * 3 + t) * N_ + i;
            float d = g_pd[base];
            int   x = g_pi[base];
            if (d < bd2) {
                if (d < bd1) {
                    bd2 = bd1; bi2 = bi1;
                    if (d < bd0) { bd1 = bd0; bi1 = bi0; bd0 = d; bi0 = x; }
                    else         { bd1 = d;   bi1 = x; }
                } else { bd2 = d; bi2 = x; }
            }
        }
    }
    float r0 = 1.f / (bd0 + 1e-8f), r1 = 1.f / (bd1 + 1e-8f), r2 = 1.f / (bd2 + 1e-8f);
    float rs = r0 + r1 + r2;
    size_t base = (size_t)b * 3 * N_ + i;
    g_idx[base + 0 * N_] = bi0; g_idx[base + 1 * N_] = bi1; g_idx[base + 2 * N_] = bi2;
    g_w[base + 0 * N_] = r0 / rs; g_w[base + 1 * N_] = r1 / rs; g_w[base + 2 * N_] = r2 / rs;
}

// ---------------- three_interpolate ----------------------------------------------
__global__ void __launch_bounds__(256) interp_kernel(const float* __restrict__ kf) {
    int b = blockIdx.y;
    int cg = blockIdx.x;
    const int*   ib = g_idx + (size_t)b * 3 * N_;
    const float* wb = g_w   + (size_t)b * 3 * N_;
    for (int i = threadIdx.x; i < N_; i += blockDim.x) {
        int i0 = ib[i], i1 = ib[i + N_], i2 = ib[i + 2 * N_];
        float w0 = wb[i], w1 = wb[i + N_], w2 = wb[i + 2 * N_];
        #pragma unroll
        for (int cc = 0; cc < 8; ++cc) {
            int c = cg * 8 + cc;
            const float* row = kf + ((size_t)b * C2_ + c) * M_;
            g_interp[((size_t)b * C2_ + c) * N_ + i] = w0 * row[i0] + w1 * row[i1] + w2 * row[i2];
        }
    }
}

// ---------------- single-pass fp16 HMMA GEMM (128x128 tiles, 2 CTAs/SM) ----------
template <int MODE>
__device__ __forceinline__ void loadB_regs(float4 xr[4], int b, int nb, int chunk,
                                           int tid, const float* __restrict__ uf) {
    int kp = tid >> 4;
    int n8 = (tid & 15) * 8;
    int k = chunk * KC + kp * 2;
    const float* r0;
    if constexpr (MODE == 0) {
        r0 = (k < C2_) ? g_interp + ((size_t)b * C2_ + k) * N_
                       : uf       + ((size_t)b * C1_ + (k - C2_)) * N_;
    } else {
        r0 = g_h1 + ((size_t)b * CO_ + k) * N_;
    }
    const float* p0 = r0 + nb + n8;
    xr[0] = *(const float4*)(p0);
    xr[1] = *(const float4*)(p0 + 4);
    xr[2] = *(const float4*)(p0 + N_);
    xr[3] = *(const float4*)(p0 + N_ + 4);
}

template <int MODE>
__device__ __forceinline__ void storeB(uint32_t* __restrict__ bs,
                                       float4 xr[4], int chunk, int tid) {
    int kp = tid >> 4;
    int n8 = (tid & 15) * 8;
    float x0[8] = {xr[0].x, xr[0].y, xr[0].z, xr[0].w, xr[1].x, xr[1].y, xr[1].z, xr[1].w};
    float x1[8] = {xr[2].x, xr[2].y, xr[2].z, xr[2].w, xr[3].x, xr[3].y, xr[3].z, xr[3].w};
    if constexpr (MODE == 1) {
        int kg = chunk * KC + kp * 2;
        float s0 = g_scale1[kg],     sh0 = g_shift1[kg];
        float s1 = g_scale1[kg + 1], sh1 = g_shift1[kg + 1];
        #pragma unroll
        for (int i = 0; i < 8; ++i) {
            x0[i] = fmaxf(fmaf(s0, x0[i], sh0), 0.f);
            x1[i] = fmaxf(fmaf(s1, x1[i], sh1), 0.f);
        }
    }
    #pragma unroll
    for (int i = 0; i < 8; ++i) {
        int n = n8 + i;
        __half h0 = __float2half_rn(x0[i]);
        __half h1 = __float2half_rn(x1[i]);
        uint32_t hw = (uint32_t)__half_as_ushort(h0) | ((uint32_t)__half_as_ushort(h1) << 16);
        int m3 = (n >> 3) & 3;
        int w = n * 20 + (((kp >> 2) ^ m3) << 2) + (kp & 3);
        bs[w] = hw;
    }
}

// A fragments via ldmatrix.x4: rows = co (32-row warp strip), 80B rows
__device__ __forceinline__ void ldA4(uint32_t a[2][4], uint32_t aBase,
                                     int wm, int lane, int ks) {
    int j = lane >> 3, rr = lane & 7;
    uint32_t koff = (uint32_t)(ks * 32 + (j >> 1) * 16);
    uint32_t rbase = (uint32_t)((wm * 32 + (j & 1) * 8 + rr) * ROWB);
    #pragma unroll
    for (int t = 0; t < 2; ++t)
        ldmx4(a[t], aBase + rbase + (uint32_t)(t * 16 * ROWB) + koff);
}
// B fragments via ldmatrix.x4: rows = n (64-row warp strip), chunk-swizzled
__device__ __forceinline__ void ldB4(uint32_t bb[16], uint32_t bBase,
                                     int wn, int lane, int ks) {
    int j = lane >> 3, rr = lane & 7;
    #pragma unroll
    for (int up = 0; up < 4; ++up) {
        int u = up * 2;
        int grp = u + (j >> 1);
        int chunk = ks * 2 + (j & 1);
        int m3 = grp & 3;
        uint32_t addr = bBase + (uint32_t)(((wn * 8 + grp) * 8 + rr) * ROWB)
                      + (uint32_t)((chunk ^ m3) * 16);
        ldmx4(&bb[u * 2], addr);
    }
}

template <int MODE>
__global__ void __launch_bounds__(256, 2) mma_gemm_kernel(const float* __restrict__ uf) {
    constexpr int Kdim = (MODE == 0) ? 512 : 256;
    constexpr int NC = Kdim / KC;

    extern __shared__ char dyn[];
    uint32_t sbase = smem_u32(dyn);

    int tid = threadIdx.x;
    int wid = tid >> 5, lane = tid & 31;
    int g = lane >> 2, tig = lane & 3;
    int wm = wid >> 1;          // 0..3, co strips of 32
    int wn = wid & 1;           // 0..1, n strips of 64
    int cot = blockIdx.x;       // co-tile 0/1 (fastest -> L2 X reuse)
    int nb  = blockIdx.y * TN;
    int b   = blockIdx.z;

    const __half* img = (MODE == 0) ? g_w1img : g_w2img;
    const char* imgbase = (const char*)img + (size_t)cot * TM * ROWB;

    float acc[2][8][4];
    #pragma unroll
    for (int t = 0; t < 2; ++t)
        #pragma unroll
        for (int u = 0; u < 8; ++u)
            #pragma unroll
            for (int v = 0; v < 4; ++v) acc[t][u][v] = 0.f;

    // cp.async of one A stage (10KB): 640 x 16B with 256 threads
    auto cpA = [&](int chunk, uint32_t dst) {
        const char* cbase = imgbase + (size_t)chunk * (256 * ROWB);
        #pragma unroll
        for (int j = 0; j < 3; ++j) {
            int v = tid + j * 256;
            if (v < 640)
                CP_ASYNC16(dst + (uint32_t)(v * 16), cbase + v * 16);
        }
    };

    // prologue: chunk 0
    {
        cpA(0, sbase);
        CP_COMMIT();
        float4 xr[4];
        loadB_regs<MODE>(xr, b, nb, 0, tid, uf);
        storeB<MODE>((uint32_t*)(dyn + B_BASE_), xr, 0, tid);
        CP_WAIT0();
        __syncthreads();
    }

    for (int c = 0; c < NC; ++c) {
        int p = c & 1, q = p ^ 1;
        float4 xr[4];
        if (c + 1 < NC) {
            cpA(c + 1, sbase + q * A_STAGE);
            CP_COMMIT();
            loadB_regs<MODE>(xr, b, nb, c + 1, tid, uf);
        }

        uint32_t AB = sbase + p * A_STAGE;
        uint32_t BB = sbase + B_BASE_ + p * B_STAGE;

        uint32_t a[2][4], bb[16];
        #pragma unroll
        for (int ks = 0; ks < 2; ++ks) {
            ldA4(a, AB, wm, lane, ks);
            ldB4(bb, BB, wn, lane, ks);
            #pragma unroll
            for (int t = 0; t < 2; ++t)
                #pragma unroll
                for (int u = 0; u < 8; ++u) mma16816(acc[t][u], a[t], &bb[u * 2]);
        }

        if (c + 1 < NC) {
            storeB<MODE>((uint32_t*)(dyn + B_BASE_ + q * B_STAGE), xr, c + 1, tid);
            CP_WAIT0();
        }
        __syncthreads();
    }

    // epilogue: store + fused BN stats
    float* out  = (MODE == 0) ? g_h1  : g_h2;
    float* gsum = (MODE == 0) ? g_sum1 : g_sum2;
    float* gsq  = (MODE == 0) ? g_sq1  : g_sq2;
    #pragma unroll
    for (int t = 0; t < 2; ++t) {
        int co0 = cot * TM + wm * 32 + t * 16 + g;
        int co1 = co0 + 8;
        float s0 = 0.f, q0 = 0.f, s1 = 0.f, q1 = 0.f;
        #pragma unroll
        for (int u = 0; u < 8; ++u) {
            int n = nb + wn * 64 + u * 8 + tig * 2;
            float2 v0 = make_float2(acc[t][u][0], acc[t][u][1]);
            float2 v1 = make_float2(acc[t][u][2], acc[t][u][3]);
            *(float2*)(out + ((size_t)b * CO_ + co0) * N_ + n) = v0;
            *(float2*)(out + ((size_t)b * CO_ + co1) * N_ + n) = v1;
            s0 += v0.x + v0.y; q0 += v0.x * v0.x + v0.y * v0.y;
            s1 += v1.x + v1.y; q1 += v1.x * v1.x + v1.y * v1.y;
        }
        #pragma unroll
        for (int o = 2; o > 0; o >>= 1) {
            s0 += __shfl_down_sync(0xffffffffu, s0, o);
            q0 += __shfl_down_sync(0xffffffffu, q0, o);
            s1 += __shfl_down_sync(0xffffffffu, s1, o);
            q1 += __shfl_down_sync(0xffffffffu, q1, o);
        }
        if (tig == 0) {
            atomicAdd(&gsum[co0], s0); atomicAdd(&gsq[co0], q0);
            atomicAdd(&gsum[co1], s1); atomicAdd(&gsq[co1], q1);
        }
    }
}

// ---------------- BN fold + final apply -----------------------------------------
template <int MODE>
__global__ void finalize_kernel(const float* __restrict__ g, const float* __restrict__ bb) {
    int c = threadIdx.x;
    float inv = 1.f / (float)(B_ * N_);
    float s  = (MODE == 0) ? g_sum1[c] : g_sum2[c];
    float sq = (MODE == 0) ? g_sq1[c]  : g_sq2[c];
    float mean = s * inv;
    float var  = sq * inv - mean * mean;
    float rstd = rsqrtf(var + 1e-5f);
    float sc = g[c] * rstd;
    float sh = bb[c] - mean * sc;
    if (MODE == 0) { g_scale1[c] = sc; g_shift1[c] = sh; }
    else           { g_scale2[c] = sc; g_shift2[c] = sh; }
}

__global__ void __launch_bounds__(256) apply_kernel(float* __restrict__ out) {
    size_t idx = (size_t)blockIdx.x * blockDim.x + threadIdx.x;
    int c = (int)((idx * 4 / N_) % CO_);
    float4 v = ((const float4*)g_h2)[idx];
    float sc = g_scale2[c], sh = g_shift2[c];
    v.x = fmaxf(fmaf(sc, v.x, sh), 0.f);
    v.y = fmaxf(fmaf(sc, v.y, sh), 0.f);
    v.z = fmaxf(fmaf(sc, v.z, sh), 0.f);
    v.w = fmaxf(fmaf(sc, v.w, sh), 0.f);
    ((float4*)out)[idx] = v;
}

// ---------------- launch ----------------------------------------------------------
extern "C" void kernel_launch(void* const* d_in, const int* in_sizes, int n_in,
                              void* d_out, int out_size) {
    const float* unknown      = (const float*)d_in[0];
    const float* known        = (const float*)d_in[1];
    const float* unknow_feats = (const float*)d_in[2];
    const float* known_feats  = (const float*)d_in[3];
    const float* W1 = (const float*)d_in[4];
    const float* g1 = (const float*)d_in[5];
    const float* b1 = (const float*)d_in[6];
    const float* W2 = (const float*)d_in[7];
    const float* g2 = (const float*)d_in[8];
    const float* b2 = (const float*)d_in[9];
    float* out = (float*)d_out;

    static bool attr_done = false;
    if (!attr_done) {
        cudaFuncSetAttribute(mma_gemm_kernel<0>, cudaFuncAttributeMaxDynamicSharedMemorySize, SMEM_TOTAL);
        cudaFuncSetAttribute(mma_gemm_kernel<1>, cudaFuncAttributeMaxDynamicSharedMemorySize, SMEM_TOTAL);
        attr_done = true;
    }

    __half* w1img; cudaGetSymbolAddress((void**)&w1img, g_w1img);
    __half* w2img; cudaGetSymbolAddress((void**)&w2img, g_w2img);
    {
        int tot1 = 16 * 256 * ROWE;
        wsplit_img_kernel<<<(tot1 + 255) / 256, 256>>>(W1, 512, tot1, w1img, 1);
        int tot2 = 8 * 256 * ROWE;
        wsplit_img_kernel<<<(tot2 + 255) / 256, 256>>>(W2, 256, tot2, w2img, 0);
    }
    knn_part_kernel<<<dim3(N_ / 512, 4, B_), 128>>>(unknown, known);
    knn_merge_kernel<<<dim3(N_ / 128, B_), 128>>>();
    interp_kernel<<<dim3(C2_ / 8, B_), 256>>>(known_feats);

    dim3 ggrid(CO_ / TM, N_ / TN, B_);
    mma_gemm_kernel<0><<<ggrid, 256, SMEM_TOTAL>>>(unknow_feats);
    finalize_kernel<0><<<1, 256>>>(g1, b1);
    mma_gemm_kernel<1><<<ggrid, 256, SMEM_TOTAL>>>(nullptr);
    finalize_kernel<1><<<1, 256>>>(g2, b2);
    apply_kernel<<<(size_t)B_ * CO_ * (N_ / 4) / 256, 256>>>(out);
}

// round 15
// speedup vs baseline: 1.0750x; 1.0750x over previous
#include <cuda_runtime.h>
#include <cuda_fp16.h>
#include <cstdint>
#include <cstddef>

#define B_   16
#define N_   4096
#define M_   1024
#define C1_  256
#define C2_  256
#define CO_  256

// GEMM tile geometry: 128co x 128n per block, 2 CTAs/SM, single-pass fp16
#define TM 128
#define TN 128
#define KC 32
#define ROWE 40               // fp16 elems per smem row (32 data + 8 pad) = 80B
#define ROWB 80
#define A_STAGE 10240         // 128 rows * 80B
#define B_BASE_ 20480
#define B_STAGE 10240
#define SMEM_TOTAL 40960

// ---------------- scratch (device globals) ------------------------------------
__device__ float g_interp[(size_t)B_ * C2_ * N_];
__device__ float g_h1[(size_t)B_ * CO_ * N_];
__device__ __half g_h2h[(size_t)B_ * CO_ * N_];     // fp16: only read by apply
__device__ int   g_idx[(size_t)B_ * 3 * N_];
__device__ float g_w[(size_t)B_ * 3 * N_];
__device__ float g_pd[(size_t)B_ * 4 * 3 * N_];
__device__ int   g_pi[(size_t)B_ * 4 * 3 * N_];
__device__ float g_sum1[CO_], g_sq1[CO_], g_scale1[CO_], g_shift1[CO_];
__device__ float g_sum2[CO_], g_sq2[CO_], g_scale2[CO_], g_shift2[CO_];
// fp16 weight smem-images: [chunk][256 co][ROWE]
__device__ __half g_w1img[16 * 256 * ROWE];
__device__ __half g_w2img[8 * 256 * ROWE];

// ---------------- helpers ------------------------------------------------------
__device__ __forceinline__ uint32_t smem_u32(const void* p) {
    uint32_t a;
    asm("{ .reg .u64 t; cvta.to.shared.u64 t, %1; cvt.u32.u64 %0, t; }" : "=r"(a) : "l"(p));
    return a;
}
#define CP_ASYNC16(dst, src) \
    asm volatile("cp.async.cg.shared.global [%0], [%1], 16;" :: "r"(dst), "l"(src))
#define CP_COMMIT() asm volatile("cp.async.commit_group;")
#define CP_WAIT0()  asm volatile("cp.async.wait_group 0;")

__device__ __forceinline__ void mma16816(float c[4], const uint32_t a[4], const uint32_t b[2]) {
    asm volatile(
        "mma.sync.aligned.m16n8k16.row.col.f32.f16.f16.f32 "
        "{%0,%1,%2,%3}, {%4,%5,%6,%7}, {%8,%9}, {%0,%1,%2,%3};"
        : "+f"(c[0]), "+f"(c[1]), "+f"(c[2]), "+f"(c[3])
        : "r"(a[0]), "r"(a[1]), "r"(a[2]), "r"(a[3]), "r"(b[0]), "r"(b[1]));
}
__device__ __forceinline__ void ldmx4(uint32_t r[4], uint32_t addr) {
    asm volatile("ldmatrix.sync.aligned.m8n8.x4.shared.b16 {%0,%1,%2,%3}, [%4];"
                 : "=r"(r[0]), "=r"(r[1]), "=r"(r[2]), "=r"(r[3]) : "r"(addr));
}

// ---------------- weight fp16 image (+stats zero folded in) ---------------------
__global__ void wsplit_img_kernel(const float* __restrict__ W, int Kdim, int total,
                                  __half* __restrict__ out, int do_zero) {
    int idx = blockIdx.x * 256 + threadIdx.x;
    if (do_zero && blockIdx.x == 0) {
        int t = threadIdx.x;
        g_sum1[t] = 0.f; g_sq1[t] = 0.f;
        g_sum2[t] = 0.f; g_sq2[t] = 0.f;
    }
    if (idx >= total) return;
    int kk = idx % ROWE;
    int co = (idx / ROWE) & 255;
    int chunk = idx / (ROWE * 256);
    float v = (kk < KC) ? W[(size_t)co * Kdim + chunk * KC + kk] : 0.f;
    out[idx] = __float2half_rn(v);
}

// ---------------- chunked three_nn ----------------------------------------------
__global__ void __launch_bounds__(128) knn_part_kernel(
    const float* __restrict__ unknown, const float* __restrict__ known) {
    __shared__ float4 sk[256];
    int b = blockIdx.z, ch = blockIdx.y;
    const float* kb = known + ((size_t)b * M_ + ch * 256) * 3;
    for (int j = threadIdx.x; j < 256; j += 128)
        sk[j] = make_float4(kb[j * 3 + 0], kb[j * 3 + 1], kb[j * 3 + 2], 0.f);
    __syncthreads();

    int i = blockIdx.x * 128 + threadIdx.x;
    const float* up = unknown + ((size_t)b * N_ + i) * 3;
    float px = up[0], py = up[1], pz = up[2];
    float bd0 = 1e30f, bd1 = 1e30f, bd2 = 1e30f;
    int   bi0 = 0, bi1 = 0, bi2 = 0;
    #pragma unroll 4
    for (int j = 0; j < 256; ++j) {
        float4 k4 = sk[j];
        float dx = px - k4.x, dy = py - k4.y, dz = pz - k4.z;
        float d = dx * dx + dy * dy + dz * dz;
        if (d < bd2) {
            if (d < bd1) {
                bd2 = bd1; bi2 = bi1;
                if (d < bd0) { bd1 = bd0; bi1 = bi0; bd0 = d; bi0 = j; }
                else         { bd1 = d;   bi1 = j; }
            } else { bd2 = d; bi2 = j; }
        }
    }
    int gofs = ch * 256;
    size_t base = (((size_t)b * 4 + ch) * 3) * N_ + i;
    g_pd[base + 0 * N_] = bd0; g_pi[base + 0 * N_] = bi0 + gofs;
    g_pd[base + 1 * N_] = bd1; g_pi[base + 1 * N_] = bi1 + gofs;
    g_pd[base + 2 * N_] = bd2; g_pi[base + 2 * N_] = bi2 + gofs;
}

__global__ void __launch_bounds__(128) knn_merge_kernel() {
    int b = blockIdx.y;
    int i = blockIdx.x * 128 + threadIdx.x;
    float bd0 = 1e30f, bd1 = 1e30f, bd2 = 1e30f;
    int   bi0 = 0, bi1 = 0, bi2 = 0;
    #pragma unroll
    for (int ch = 0; ch < 4; ++ch) {
        #pragma unroll
        for (int t = 0; t < 3; ++t) {
            size_t base = (((size_t)b * 4 + ch) * 3 + t) * N_ + i;
            float d = g_pd[base];
            int   x = g_pi[base];
            if (d < bd2) {
                if (d < bd1) {
                    bd2 = bd1; bi2 = bi1;
                    if (d < bd0) { bd1 = bd0; bi1 = bi0; bd0 = d; bi0 = x; }
                    else         { bd1 = d;   bi1 = x; }
                } else { bd2 = d; bi2 = x; }
            }
        }
    }
    float r0 = 1.f / (bd0 + 1e-8f), r1 = 1.f / (bd1 + 1e-8f), r2 = 1.f / (bd2 + 1e-8f);
    float rs = r0 + r1 + r2;
    size_t base = (size_t)b * 3 * N_ + i;
    g_idx[base + 0 * N_] = bi0; g_idx[base + 1 * N_] = bi1; g_idx[base + 2 * N_] = bi2;
    g_w[base + 0 * N_] = r0 / rs; g_w[base + 1 * N_] = r1 / rs; g_w[base + 2 * N_] = r2 / rs;
}

// ---------------- three_interpolate ----------------------------------------------
__global__ void __launch_bounds__(256) interp_kernel(const float* __restrict__ kf) {
    int b = blockIdx.y;
    int cg = blockIdx.x;
    const int*   ib = g_idx + (size_t)b * 3 * N_;
    const float* wb = g_w   + (size_t)b * 3 * N_;
    for (int i = threadIdx.x; i < N_; i += blockDim.x) {
        int i0 = ib[i], i1 = ib[i + N_], i2 = ib[i + 2 * N_];
        float w0 = wb[i], w1 = wb[i + N_], w2 = wb[i + 2 * N_];
        #pragma unroll
        for (int cc = 0; cc < 8; ++cc) {
            int c = cg * 8 + cc;
            const float* row = kf + ((size_t)b * C2_ + c) * M_;
            g_interp[((size_t)b * C2_ + c) * N_ + i] = w0 * row[i0] + w1 * row[i1] + w2 * row[i2];
        }
    }
}

// ---------------- single-pass fp16 HMMA GEMM (128x128 tiles, 2 CTAs/SM) ----------
template <int MODE>
__device__ __forceinline__ void loadB_regs(float4 xr[4], int b, int nb, int chunk,
                                           int tid, const float* __restrict__ uf) {
    int kp = tid >> 4;
    int n8 = (tid & 15) * 8;
    int k = chunk * KC + kp * 2;
    const float* r0;
    if constexpr (MODE == 0) {
        r0 = (k < C2_) ? g_interp + ((size_t)b * C2_ + k) * N_
                       : uf       + ((size_t)b * C1_ + (k - C2_)) * N_;
    } else {
        r0 = g_h1 + ((size_t)b * CO_ + k) * N_;
    }
    const float* p0 = r0 + nb + n8;
    xr[0] = *(const float4*)(p0);
    xr[1] = *(const float4*)(p0 + 4);
    xr[2] = *(const float4*)(p0 + N_);
    xr[3] = *(const float4*)(p0 + N_ + 4);
}

template <int MODE>
__device__ __forceinline__ void storeB(uint32_t* __restrict__ bs,
                                       float4 xr[4], int chunk, int tid) {
    int kp = tid >> 4;
    int n8 = (tid & 15) * 8;
    float x0[8] = {xr[0].x, xr[0].y, xr[0].z, xr[0].w, xr[1].x, xr[1].y, xr[1].z, xr[1].w};
    float x1[8] = {xr[2].x, xr[2].y, xr[2].z, xr[2].w, xr[3].x, xr[3].y, xr[3].z, xr[3].w};
    if constexpr (MODE == 1) {
        int kg = chunk * KC + kp * 2;
        float s0 = g_scale1[kg],     sh0 = g_shift1[kg];
        float s1 = g_scale1[kg + 1], sh1 = g_shift1[kg + 1];
        #pragma unroll
        for (int i = 0; i < 8; ++i) {
            x0[i] = fmaxf(fmaf(s0, x0[i], sh0), 0.f);
            x1[i] = fmaxf(fmaf(s1, x1[i], sh1), 0.f);
        }
    }
    #pragma unroll
    for (int i = 0; i < 8; ++i) {
        int n = n8 + i;
        __half h0 = __float2half_rn(x0[i]);
        __half h1 = __float2half_rn(x1[i]);
        uint32_t hw = (uint32_t)__half_as_ushort(h0) | ((uint32_t)__half_as_ushort(h1) << 16);
        int m3 = (n >> 3) & 3;
        int w = n * 20 + (((kp >> 2) ^ m3) << 2) + (kp & 3);
        bs[w] = hw;
    }
}

// A fragments via ldmatrix.x4: rows = co (32-row warp strip), 80B rows
__device__ __forceinline__ void ldA4(uint32_t a[2][4], uint32_t aBase,
                                     int wm, int lane, int ks) {
    int j = lane >> 3, rr = lane & 7;
    uint32_t koff = (uint32_t)(ks * 32 + (j >> 1) * 16);
    uint32_t rbase = (uint32_t)((wm * 32 + (j & 1) * 8 + rr) * ROWB);
    #pragma unroll
    for (int t = 0; t < 2; ++t)
        ldmx4(a[t], aBase + rbase + (uint32_t)(t * 16 * ROWB) + koff);
}
// B fragments via ldmatrix.x4: rows = n (64-row warp strip), chunk-swizzled
__device__ __forceinline__ void ldB4(uint32_t bb[16], uint32_t bBase,
                                     int wn, int lane, int ks) {
    int j = lane >> 3, rr = lane & 7;
    #pragma unroll
    for (int up = 0; up < 4; ++up) {
        int u = up * 2;
        int grp = u + (j >> 1);
        int chunk = ks * 2 + (j & 1);
        int m3 = grp & 3;
        uint32_t addr = bBase + (uint32_t)(((wn * 8 + grp) * 8 + rr) * ROWB)
                      + (uint32_t)((chunk ^ m3) * 16);
        ldmx4(&bb[u * 2], addr);
    }
}

template <int MODE>
__global__ void __launch_bounds__(256, 2) mma_gemm_kernel(const float* __restrict__ uf) {
    constexpr int Kdim = (MODE == 0) ? 512 : 256;
    constexpr int NC = Kdim / KC;

    extern __shared__ char dyn[];
    uint32_t sbase = smem_u32(dyn);

    int tid = threadIdx.x;
    int wid = tid >> 5, lane = tid & 31;
    int g = lane >> 2, tig = lane & 3;
    int wm = wid >> 1;          // 0..3, co strips of 32
    int wn = wid & 1;           // 0..1, n strips of 64
    int cot = blockIdx.x;       // co-tile 0/1 (fastest -> L2 X reuse)
    int nb  = blockIdx.y * TN;
    int b   = blockIdx.z;

    const __half* img = (MODE == 0) ? g_w1img : g_w2img;
    const char* imgbase = (const char*)img + (size_t)cot * TM * ROWB;

    float acc[2][8][4];
    #pragma unroll
    for (int t = 0; t < 2; ++t)
        #pragma unroll
        for (int u = 0; u < 8; ++u)
            #pragma unroll
            for (int v = 0; v < 4; ++v) acc[t][u][v] = 0.f;

    // cp.async of one A stage (10KB): 640 x 16B with 256 threads
    auto cpA = [&](int chunk, uint32_t dst) {
        const char* cbase = imgbase + (size_t)chunk * (256 * ROWB);
        #pragma unroll
        for (int j = 0; j < 3; ++j) {
            int v = tid + j * 256;
            if (v < 640)
                CP_ASYNC16(dst + (uint32_t)(v * 16), cbase + v * 16);
        }
    };

    // prologue: chunk 0
    {
        cpA(0, sbase);
        CP_COMMIT();
        float4 xr[4];
        loadB_regs<MODE>(xr, b, nb, 0, tid, uf);
        storeB<MODE>((uint32_t*)(dyn + B_BASE_), xr, 0, tid);
        CP_WAIT0();
        __syncthreads();
    }

    for (int c = 0; c < NC; ++c) {
        int p = c & 1, q = p ^ 1;
        float4 xr[4];
        if (c + 1 < NC) {
            cpA(c + 1, sbase + q * A_STAGE);
            CP_COMMIT();
            loadB_regs<MODE>(xr, b, nb, c + 1, tid, uf);
        }

        uint32_t AB = sbase + p * A_STAGE;
        uint32_t BB = sbase + B_BASE_ + p * B_STAGE;

        uint32_t a[2][4], bb[16];
        #pragma unroll
        for (int ks = 0; ks < 2; ++ks) {
            ldA4(a, AB, wm, lane, ks);
            ldB4(bb, BB, wn, lane, ks);
            #pragma unroll
            for (int t = 0; t < 2; ++t)
                #pragma unroll
                for (int u = 0; u < 8; ++u) mma16816(acc[t][u], a[t], &bb[u * 2]);
        }

        if (c + 1 < NC) {
            storeB<MODE>((uint32_t*)(dyn + B_BASE_ + q * B_STAGE), xr, c + 1, tid);
            CP_WAIT0();
        }
        __syncthreads();
    }

    // epilogue: store + fused BN stats (h1 fp32; h2 fp16)
    float* gsum = (MODE == 0) ? g_sum1 : g_sum2;
    float* gsq  = (MODE == 0) ? g_sq1  : g_sq2;
    #pragma unroll
    for (int t = 0; t < 2; ++t) {
        int co0 = cot * TM + wm * 32 + t * 16 + g;
        int co1 = co0 + 8;
        float s0 = 0.f, q0 = 0.f, s1 = 0.f, q1 = 0.f;
        #pragma unroll
        for (int u = 0; u < 8; ++u) {
            int n = nb + wn * 64 + u * 8 + tig * 2;
            float va = acc[t][u][0], vb = acc[t][u][1];
            float vc = acc[t][u][2], vd = acc[t][u][3];
            if constexpr (MODE == 0) {
                *(float2*)(g_h1 + ((size_t)b * CO_ + co0) * N_ + n) = make_float2(va, vb);
                *(float2*)(g_h1 + ((size_t)b * CO_ + co1) * N_ + n) = make_float2(vc, vd);
            } else {
                *(__half2*)(g_h2h + ((size_t)b * CO_ + co0) * N_ + n) = __floats2half2_rn(va, vb);
                *(__half2*)(g_h2h + ((size_t)b * CO_ + co1) * N_ + n) = __floats2half2_rn(vc, vd);
            }
            s0 += va + vb; q0 += va * va + vb * vb;
            s1 += vc + vd; q1 += vc * vc + vd * vd;
        }
        #pragma unroll
        for (int o = 2; o > 0; o >>= 1) {
            s0 += __shfl_down_sync(0xffffffffu, s0, o);
            q0 += __shfl_down_sync(0xffffffffu, q0, o);
            s1 += __shfl_down_sync(0xffffffffu, s1, o);
            q1 += __shfl_down_sync(0xffffffffu, q1, o);
        }
        if (tig == 0) {
            atomicAdd(&gsum[co0], s0); atomicAdd(&gsq[co0], q0);
            atomicAdd(&gsum[co1], s1); atomicAdd(&gsq[co1], q1);
        }
    }
}

// ---------------- BN fold + final apply -----------------------------------------
template <int MODE>
__global__ void finalize_kernel(const float* __restrict__ g, const float* __restrict__ bb) {
    int c = threadIdx.x;
    float inv = 1.f / (float)(B_ * N_);
    float s  = (MODE == 0) ? g_sum1[c] : g_sum2[c];
    float sq = (MODE == 0) ? g_sq1[c]  : g_sq2[c];
    float mean = s * inv;
    float var  = sq * inv - mean * mean;
    float rstd = rsqrtf(var + 1e-5f);
    float sc = g[c] * rstd;
    float sh = bb[c] - mean * sc;
    if (MODE == 0) { g_scale1[c] = sc; g_shift1[c] = sh; }
    else           { g_scale2[c] = sc; g_shift2[c] = sh; }
}

__global__ void __launch_bounds__(256) apply_kernel(float* __restrict__ out) {
    size_t idx = (size_t)blockIdx.x * blockDim.x + threadIdx.x;  // 4 elems each
    int c = (int)((idx * 4 / N_) % CO_);
    uint2 hv = *(const uint2*)(g_h2h + idx * 4);
    float2 f0 = __half22float2(*(__half2*)&hv.x);
    float2 f1 = __half22float2(*(__half2*)&hv.y);
    float sc = g_scale2[c], sh = g_shift2[c];
    float4 v;
    v.x = fmaxf(fmaf(sc, f0.x, sh), 0.f);
    v.y = fmaxf(fmaf(sc, f0.y, sh), 0.f);
    v.z = fmaxf(fmaf(sc, f1.x, sh), 0.f);
    v.w = fmaxf(fmaf(sc, f1.y, sh), 0.f);
    ((float4*)out)[idx] = v;
}

// ---------------- launch ----------------------------------------------------------
extern "C" void kernel_launch(void* const* d_in, const int* in_sizes, int n_in,
                              void* d_out, int out_size) {
    const float* unknown      = (const float*)d_in[0];
    const float* known        = (const float*)d_in[1];
    const float* unknow_feats = (const float*)d_in[2];
    const float* known_feats  = (const float*)d_in[3];
    const float* W1 = (const float*)d_in[4];
    const float* g1 = (const float*)d_in[5];
    const float* b1 = (const float*)d_in[6];
    const float* W2 = (const float*)d_in[7];
    const float* g2 = (const float*)d_in[8];
    const float* b2 = (const float*)d_in[9];
    float* out = (float*)d_out;

    static bool attr_done = false;
    if (!attr_done) {
        cudaFuncSetAttribute(mma_gemm_kernel<0>, cudaFuncAttributeMaxDynamicSharedMemorySize, SMEM_TOTAL);
        cudaFuncSetAttribute(mma_gemm_kernel<1>, cudaFuncAttributeMaxDynamicSharedMemorySize, SMEM_TOTAL);
        attr_done = true;
    }

    __half* w1img; cudaGetSymbolAddress((void**)&w1img, g_w1img);
    __half* w2img; cudaGetSymbolAddress((void**)&w2img, g_w2img);
    {
        int tot1 = 16 * 256 * ROWE;
        wsplit_img_kernel<<<(tot1 + 255) / 256, 256>>>(W1, 512, tot1, w1img, 1);
        int tot2 = 8 * 256 * ROWE;
        wsplit_img_kernel<<<(tot2 + 255) / 256, 256>>>(W2, 256, tot2, w2img, 0);
    }
    knn_part_kernel<<<dim3(N_ / 128, 4, B_), 128>>>(unknown, known);
    knn_merge_kernel<<<dim3(N_ / 128, B_), 128>>>();
    interp_kernel<<<dim3(C2_ / 8, B_), 256>>>(known_feats);

    dim3 ggrid(CO_ / TM, N_ / TN, B_);
    mma_gemm_kernel<0><<<ggrid, 256, SMEM_TOTAL>>>(unknow_feats);
    finalize_kernel<0><<<1, 256>>>(g1, b1);
    mma_gemm_kernel<1><<<ggrid, 256, SMEM_TOTAL>>>(nullptr);
    finalize_kernel<1><<<1, 256>>>(g2, b2);
    apply_kernel<<<(size_t)B_ * CO_ * (N_ / 4) / 256, 256>>>(out);
}